// round 8
// baseline (speedup 1.0000x reference)
#include <cuda_runtime.h>
#include <cstdint>

#define D_MODEL 1024
#define NH 16
#define DK 64
#define BATCH 2
#define SEQ 2048
#define ROWS (BATCH*SEQ)

// Q prescale: (1/sqrt(64)) * log2(e)
#define QSCALE 0.18033688011112042f

// ---- scratch (no allocations allowed) ----
__device__ __align__(16) float g_xt [ROWS * 1024];
__device__ __align__(16) float g_wqt[1024 * 1024];
__device__ __align__(16) float g_wkt[256  * 1024];
__device__ __align__(16) float g_wvt[256  * 1024];
__device__ __align__(16) float g_wot[1024 * 1024];
__device__ __align__(16) float g_q  [ROWS * 1024];
__device__ __align__(16) float g_k  [ROWS * 256];
__device__ __align__(16) float g_vt [256  * ROWS];
__device__ __align__(16) float g_o  [ROWS * 1024];

__device__ __forceinline__ uint32_t f2tf(float x) {
    uint32_t y;
    asm("cvt.rna.tf32.f32 %0, %1;" : "=r"(y) : "f"(x));
    return y;
}
__device__ __forceinline__ float rndf(float x) { return __uint_as_float(f2tf(x)); }
__device__ __forceinline__ float ex2(float x) {
    float y;
    asm("ex2.approx.ftz.f32 %0, %1;" : "=f"(y) : "f"(x));
    return y;
}

// permuted position j (0..63) <-> feature k: j = tg*16 + kk*2 + s, k = kk*8 + tg + 4s
__device__ __forceinline__ int j16(int k)   { return (k & 3) * 16 + ((k >> 3) << 1) + ((k >> 2) & 1); }
__device__ __forceinline__ int sig64(int j) { return (((j >> 1) & 7) << 3) + (j >> 4) + ((j & 1) << 2); }

__device__ __forceinline__ void mma8(float* c, const uint32_t* a, const uint32_t* b) {
    asm volatile(
        "mma.sync.aligned.m16n8k8.row.col.f32.tf32.tf32.f32 "
        "{%0,%1,%2,%3},{%4,%5,%6,%7},{%8,%9},{%0,%1,%2,%3};"
        : "+f"(c[0]), "+f"(c[1]), "+f"(c[2]), "+f"(c[3])
        : "r"(a[0]), "r"(a[1]), "r"(a[2]), "r"(a[3]), "r"(b[0]), "r"(b[1]));
}

__device__ __forceinline__ void cpa16(uint32_t dst, const void* src) {
    asm volatile("cp.async.cg.shared.global [%0], [%1], 16;\n" :: "r"(dst), "l"(src) : "memory");
}
#define CP_COMMIT asm volatile("cp.async.commit_group;\n" ::: "memory")
#define CP_WAIT1  asm volatile("cp.async.wait_group 1;\n" ::: "memory")
#define CP_WAIT0  asm volatile("cp.async.wait_group 0;\n" ::: "memory")

#define GP 20
#define GPITCH 80

// ============================================================
// Prepass kernels
// ============================================================
__global__ __launch_bounds__(256) void prep_act(const float* __restrict__ in, float* __restrict__ out) {
    int i4 = (blockIdx.x * 256 + threadIdx.x) * 4;
    int base = i4 & ~63;
#pragma unroll
    for (int j = 0; j < 4; j++)
        out[i4 + j] = rndf(in[base + sig64((i4 + j) & 63)]);
}

__global__ __launch_bounds__(256) void prep_w(
    const float* __restrict__ Wq, const float* __restrict__ Wk,
    const float* __restrict__ Wv, const float* __restrict__ Wo)
{
    int col = blockIdx.x * 256 + threadIdx.x;
    int kp = blockIdx.y;
    int k = (kp & ~63) + sig64(kp & 63);
    const float* W; float* Wt; int N, n;
    if (col < 1024)      { W = Wq; Wt = g_wqt; N = 1024; n = col; }
    else if (col < 1280) { W = Wk; Wt = g_wkt; N = 256;  n = col - 1024; }
    else if (col < 1536) { W = Wv; Wt = g_wvt; N = 256;  n = col - 1280; }
    else                 { W = Wo; Wt = g_wot; N = 1024; n = col - 1536; }
    Wt[(size_t)n * 1024 + kp] = rndf(W[(size_t)k * N + n]);
}

// ============================================================
// GEMM: C[M,N] = A[M,1024] @ Bt[N,1024]^T + bias
// Block 128(M) x 64(N), 4 warps (2x2) of 64x32.
// A-fragments via direct LDG.128 from pre-permuted global (L2-resident);
// B cp.async double-buffered in SMEM (40KB) -> 3 blocks/SM.
// ============================================================
#define BSTG (64 * GPITCH)   // words per B stage

__device__ __forceinline__ void cp_stage_B(uint32_t sb, const float* Bp, int tid) {
#pragma unroll
    for (int t = 0; t < 8; t++) {
        int cid = tid + t * 128; int row = cid >> 4, ch = cid & 15;
        cpa16(sb + (uint32_t)(row * GPITCH + (ch >> 2) * GP + (ch & 3) * 4) * 4,
              Bp + (size_t)row * 1024 + ch * 4);
    }
    CP_COMMIT;
}

template<int EPI>
__device__ __forceinline__ void gemm_body(
    const float* __restrict__ A, const float* __restrict__ Bt,
    const float* __restrict__ bias, float* __restrict__ C,
    int N, int bm, int bn)
{
    extern __shared__ uint32_t smg[];
    const int tid = threadIdx.x, lane = tid & 31, w = tid >> 5;
    const int g = lane >> 2, tg = lane & 3;
    const int wm = (w >> 1) * 64, wn = (w & 1) * 32;
    uint32_t sbase = (uint32_t)__cvta_generic_to_shared(smg);
    const float* Bb = Bt + (size_t)bn * 1024;

    float acc[4][4][4];
#pragma unroll
    for (int i = 0; i < 4; i++)
#pragma unroll
        for (int j = 0; j < 4; j++)
#pragma unroll
            for (int q = 0; q < 4; q++) acc[i][j][q] = 0.f;

    // A fragment row pointers (pre-permuted global layout)
    const uint4* arow[4][2];
#pragma unroll
    for (int mf = 0; mf < 4; mf++)
#pragma unroll
        for (int rr = 0; rr < 2; rr++) {
            int row = bm + wm + mf * 16 + g + rr * 8;
            arow[mf][rr] = (const uint4*)(A + (size_t)row * 1024 + tg * 16);
        }

    cp_stage_B(sbase, Bb, tid);
    for (int kt = 0; kt < 16; kt++) {
        if (kt < 15) {
            cp_stage_B(sbase + (uint32_t)(((kt + 1) & 1) * BSTG * 4),
                       Bb + (kt + 1) * 64, tid);
            CP_WAIT1;
        } else {
            CP_WAIT0;
        }
        __syncthreads();
        const uint32_t* Ss = smg + (kt & 1) * BSTG;
        const int ao = kt * 16;   // uint4 offset of this k-tile within a row

#pragma unroll
        for (int hh = 0; hh < 2; hh++) {
            uint4 b4[4][2];
#pragma unroll
            for (int nf = 0; nf < 4; nf++) {
                const uint4* p = (const uint4*)(Ss + (wn + nf * 8 + g) * GPITCH + tg * GP + hh * 8);
                b4[nf][0] = p[0]; b4[nf][1] = p[1];
            }
#pragma unroll
            for (int mf = 0; mf < 4; mf++) {
                uint4 lo[2], hi[2];
                lo[0] = arow[mf][0][ao + hh * 2];
                lo[1] = arow[mf][0][ao + hh * 2 + 1];
                hi[0] = arow[mf][1][ao + hh * 2];
                hi[1] = arow[mf][1][ao + hh * 2 + 1];
#pragma unroll
                for (int kkl = 0; kkl < 4; kkl++) {
                    int q = kkl >> 1; bool od = kkl & 1;
                    uint32_t a[4];
                    a[0] = od ? lo[q].z : lo[q].x;
                    a[2] = od ? lo[q].w : lo[q].y;
                    a[1] = od ? hi[q].z : hi[q].x;
                    a[3] = od ? hi[q].w : hi[q].y;
#pragma unroll
                    for (int nf = 0; nf < 4; nf++) {
                        uint32_t b[2];
                        b[0] = od ? b4[nf][q].z : b4[nf][q].x;
                        b[1] = od ? b4[nf][q].w : b4[nf][q].y;
                        mma8(acc[mf][nf], a, b);
                    }
                }
            }
        }
        __syncthreads();
    }

#pragma unroll
    for (int mf = 0; mf < 4; mf++)
#pragma unroll
        for (int nf = 0; nf < 4; nf++) {
            int r0 = bm + wm + mf * 16 + g;
            int c0 = bn + wn + nf * 8 + tg * 2;
            float b0 = bias[c0], b1 = bias[c0 + 1];
            float v00 = acc[mf][nf][0] + b0, v01 = acc[mf][nf][1] + b1;
            float v10 = acc[mf][nf][2] + b0, v11 = acc[mf][nf][3] + b1;
            if (EPI == 0) {
                C[(size_t)r0 * N + c0]           = v00;
                C[(size_t)r0 * N + c0 + 1]       = v01;
                C[(size_t)(r0 + 8) * N + c0]     = v10;
                C[(size_t)(r0 + 8) * N + c0 + 1] = v11;
            } else if (EPI == 1 || EPI == 3) {
                if (EPI == 3) { v00 *= QSCALE; v01 *= QSCALE; v10 *= QSCALE; v11 *= QSCALE; }
                int cb = c0 & ~63;
                int ja = cb + j16(c0 & 63), jb = cb + j16((c0 + 1) & 63);
                C[(size_t)r0 * N + ja]       = rndf(v00);
                C[(size_t)r0 * N + jb]       = rndf(v01);
                C[(size_t)(r0 + 8) * N + ja] = rndf(v10);
                C[(size_t)(r0 + 8) * N + jb] = rndf(v11);
            } else {  // V transpose: g_vt[feature][token-permuted]
                int ra = (r0 & ~63) + j16(r0 & 63);
                int rb = (r0 & ~63) + j16((r0 + 8) & 63);
                C[(size_t)c0 * ROWS + ra]       = rndf(v00);
                C[(size_t)(c0 + 1) * ROWS + ra] = rndf(v01);
                C[(size_t)c0 * ROWS + rb]       = rndf(v10);
                C[(size_t)(c0 + 1) * ROWS + rb] = rndf(v11);
            }
        }
}

// fused Q/K/V projection: grid.x = 16 (Q) + 4 (K) + 4 (V) = 24 N-blocks of 64
__global__ __launch_bounds__(128, 3) void qkv_gemm(
    const float* __restrict__ bq, const float* __restrict__ bk, const float* __restrict__ bv)
{
    int bx = blockIdx.x, bm = blockIdx.y * 128;
    if (bx < 16)      gemm_body<3>(g_xt, g_wqt, bq, g_q,  1024, bm, bx * 64);
    else if (bx < 20) gemm_body<1>(g_xt, g_wkt, bk, g_k,  256,  bm, (bx - 16) * 64);
    else              gemm_body<2>(g_xt, g_wvt, bv, g_vt, 256,  bm, (bx - 20) * 64);
}

__global__ __launch_bounds__(128, 3) void o_gemm(const float* __restrict__ bo, float* __restrict__ out)
{
    gemm_body<0>(g_o, g_wot, bo, out, 1024, blockIdx.y * 128, blockIdx.x * 64);
}

// ============================================================
// Flash attention (round-6 best config): one-pass softmax,
// per-k-pair pipeline, 128 threads (4 warps x 32 q-rows), Q-tile 128,
// KV-tile 64, cp.async double buffer, 2 blocks/SM.
// grid (SEQ/128, NH, BATCH).
// ============================================================
#define ASTG (128 * GPITCH)   // words per stage (K 64 rows + V 64 rows)

__device__ __forceinline__ void cp_stage_attn(uint32_t sb, const float* Kp, const float* Vp, int tid) {
#pragma unroll
    for (int t = 0; t < 8; t++) {
        int cid = tid + t * 128; int row = cid >> 4, ch = cid & 15;
        cpa16(sb + (uint32_t)(row * GPITCH + (ch >> 2) * GP + (ch & 3) * 4) * 4,
              Kp + (size_t)row * 256 + ch * 4);
    }
#pragma unroll
    for (int t = 0; t < 8; t++) {
        int cid = tid + t * 128; int row = cid >> 4, ch = cid & 15;
        cpa16(sb + (uint32_t)((64 + row) * GPITCH + (ch >> 2) * GP + (ch & 3) * 4) * 4,
              Vp + (size_t)row * ROWS + ch * 4);
    }
    CP_COMMIT;
}

__global__ __launch_bounds__(128, 2) void flash_attn()
{
    extern __shared__ uint32_t sm[];
    const int qt = blockIdx.x, h = blockIdx.y, b = blockIdx.z;
    const int kvh = h >> 2;
    const int tid = threadIdx.x, lane = tid & 31, w = tid >> 5;
    const int g = lane >> 2, tg = lane & 3;
    const int q0 = w * 32;
    uint32_t sbase = (uint32_t)__cvta_generic_to_shared(sm);
    const int srcA = (lane & ~3) + (tg >> 1), srcB = srcA + 2;
    const bool oddt = tg & 1;

    // Q fragments from permuted+prescaled g_q
    uint32_t aQ[2][8][4];
#pragma unroll
    for (int mf = 0; mf < 2; mf++)
#pragma unroll
        for (int rr = 0; rr < 2; rr++) {
            int row = b * SEQ + qt * 128 + q0 + mf * 16 + g + rr * 8;
            const uint4* qp = (const uint4*)(g_q + (size_t)row * 1024 + h * 64 + tg * 16);
            uint4 u[4] = {qp[0], qp[1], qp[2], qp[3]};
#pragma unroll
            for (int q = 0; q < 4; q++) {
                aQ[mf][2 * q][rr]         = __float_as_uint(((const float*)&u[q])[0]);
                aQ[mf][2 * q][2 + rr]     = __float_as_uint(((const float*)&u[q])[1]);
                aQ[mf][2 * q + 1][rr]     = __float_as_uint(((const float*)&u[q])[2]);
                aQ[mf][2 * q + 1][2 + rr] = __float_as_uint(((const float*)&u[q])[3]);
            }
        }

    float accO[2][8][4];
#pragma unroll
    for (int mf = 0; mf < 2; mf++)
#pragma unroll
        for (int i = 0; i < 8; i++)
#pragma unroll
            for (int j = 0; j < 4; j++) accO[mf][i][j] = 0.f;
    float lsum[2][2] = {{0.f, 0.f}, {0.f, 0.f}};

    const float* Kbase = g_k + (size_t)(b * SEQ) * 256 + kvh * 64;
    const float* Vbase = g_vt + (size_t)(kvh * 64) * ROWS + (size_t)b * SEQ;

    cp_stage_attn(sbase, Kbase, Vbase, tid);
    for (int kt = 0; kt < SEQ / 64; kt++) {
        if (kt < SEQ / 64 - 1) {
            cp_stage_attn(sbase + (uint32_t)(((kt + 1) & 1) * ASTG * 4),
                          Kbase + (size_t)(kt + 1) * 64 * 256, Vbase + (kt + 1) * 64, tid);
            CP_WAIT1;
        } else {
            CP_WAIT0;
        }
        __syncthreads();
        const uint32_t* Ks = sm + (kt & 1) * ASTG;
        const uint32_t* Vs = Ks + 64 * GPITCH;

        float s[2][2][2][4];

        // ---- QK pair 0 into buf 0 ----
#pragma unroll
        for (int nl = 0; nl < 2; nl++) {
            const uint4* kp = (const uint4*)(Ks + (nl * 8 + g) * GPITCH + tg * GP);
            uint4 kf[4] = {kp[0], kp[1], kp[2], kp[3]};
#pragma unroll
            for (int q = 0; q < 4; q++) { s[0][0][nl][q] = 0.f; s[0][1][nl][q] = 0.f; }
#pragma unroll
            for (int kk = 0; kk < 8; kk++) {
                const uint4& f = kf[kk >> 1];
                uint32_t bb[2];
                bb[0] = (kk & 1) ? f.z : f.x;
                bb[1] = (kk & 1) ? f.w : f.y;
                mma8(s[0][0][nl], aQ[0][kk], bb);
                mma8(s[0][1][nl], aQ[1][kk], bb);
            }
        }

#pragma unroll
        for (int jp = 0; jp < 4; jp++) {
            const int cur = jp & 1, nxt = cur ^ 1;
            if (jp < 3) {
#pragma unroll
                for (int nl = 0; nl < 2; nl++) {
                    int nf = (jp + 1) * 2 + nl;
                    const uint4* kp = (const uint4*)(Ks + (nf * 8 + g) * GPITCH + tg * GP);
                    uint4 kf[4] = {kp[0], kp[1], kp[2], kp[3]};
#pragma unroll
                    for (int q = 0; q < 4; q++) { s[nxt][0][nl][q] = 0.f; s[nxt][1][nl][q] = 0.f; }
#pragma unroll
                    for (int kk = 0; kk < 8; kk++) {
                        const uint4& f = kf[kk >> 1];
                        uint32_t bb[2];
                        bb[0] = (kk & 1) ? f.z : f.x;
                        bb[1] = (kk & 1) ? f.w : f.y;
                        mma8(s[nxt][0][nl], aQ[0][kk], bb);
                        mma8(s[nxt][1][nl], aQ[1][kk], bb);
                    }
                }
            }

#pragma unroll
            for (int mf = 0; mf < 2; mf++)
#pragma unroll
                for (int nl = 0; nl < 2; nl++) {
                    float p0 = ex2(s[cur][mf][nl][0]);
                    float p1 = ex2(s[cur][mf][nl][1]);
                    float p2 = ex2(s[cur][mf][nl][2]);
                    float p3 = ex2(s[cur][mf][nl][3]);
                    lsum[mf][0] += p0 + p1;
                    lsum[mf][1] += p2 + p3;
                    uint32_t t0 = f2tf(p0), t1 = f2tf(p1), t2 = f2tf(p2), t3 = f2tf(p3);
                    uint32_t u0 = __shfl_sync(0xffffffffu, t0, srcA);
                    uint32_t u1 = __shfl_sync(0xffffffffu, t1, srcA);
                    uint32_t w0 = __shfl_sync(0xffffffffu, t0, srcB);
                    uint32_t w1 = __shfl_sync(0xffffffffu, t1, srcB);
                    uint32_t v0 = __shfl_sync(0xffffffffu, t2, srcA);
                    uint32_t v1 = __shfl_sync(0xffffffffu, t3, srcA);
                    uint32_t x0 = __shfl_sync(0xffffffffu, t2, srcB);
                    uint32_t x1 = __shfl_sync(0xffffffffu, t3, srcB);
                    s[cur][mf][nl][0] = __uint_as_float(oddt ? u1 : u0);
                    s[cur][mf][nl][2] = __uint_as_float(oddt ? w1 : w0);
                    s[cur][mf][nl][1] = __uint_as_float(oddt ? v1 : v0);
                    s[cur][mf][nl][3] = __uint_as_float(oddt ? x1 : x0);
                }

#pragma unroll
            for (int nf = 0; nf < 8; nf++) {
                const uint4* vp = (const uint4*)(Vs + (nf * 8 + g) * GPITCH + tg * GP);
                uint4 vf = vp[jp];
                uint32_t bb0[2] = {vf.x, vf.y};
                uint32_t bb1[2] = {vf.z, vf.w};
                mma8(accO[0][nf], (const uint32_t*)s[cur][0][0], bb0);
                mma8(accO[0][nf], (const uint32_t*)s[cur][0][1], bb1);
                mma8(accO[1][nf], (const uint32_t*)s[cur][1][0], bb0);
                mma8(accO[1][nf], (const uint32_t*)s[cur][1][1], bb1);
            }
        }
        __syncthreads();
    }

    // epilogue: quad-reduce row sums, normalize, round, write permuted into g_o
#pragma unroll
    for (int mf = 0; mf < 2; mf++) {
        float l0 = lsum[mf][0], l1 = lsum[mf][1];
        l0 += __shfl_xor_sync(0xffffffffu, l0, 1);
        l0 += __shfl_xor_sync(0xffffffffu, l0, 2);
        l1 += __shfl_xor_sync(0xffffffffu, l1, 1);
        l1 += __shfl_xor_sync(0xffffffffu, l1, 2);
        float inv0 = 1.f / l0, inv1 = 1.f / l1;
        int rbase = b * SEQ + qt * 128 + q0 + mf * 16 + g;
        float* Op = g_o + (size_t)rbase * 1024 + h * 64;
#pragma unroll
        for (int nf = 0; nf < 8; nf++) {
            int c = nf * 8 + tg * 2;
            int ja = j16(c), jb = j16(c + 1);
            Op[ja] = rndf(accO[mf][nf][0] * inv0);
            Op[jb] = rndf(accO[mf][nf][1] * inv0);
            Op[(size_t)8 * 1024 + ja] = rndf(accO[mf][nf][2] * inv1);
            Op[(size_t)8 * 1024 + jb] = rndf(accO[mf][nf][3] * inv1);
        }
    }
}

// ============================================================
extern "C" void kernel_launch(void* const* d_in, const int* in_sizes, int n_in,
                              void* d_out, int out_size)
{
    const float* x  = (const float*)d_in[0];
    const float* Wq = (const float*)d_in[1];
    const float* bq = (const float*)d_in[2];
    const float* Wk = (const float*)d_in[3];
    const float* bk = (const float*)d_in[4];
    const float* Wv = (const float*)d_in[5];
    const float* bv = (const float*)d_in[6];
    const float* Wo = (const float*)d_in[7];
    const float* bo = (const float*)d_in[8];
    float* out = (float*)d_out;

    float* xt;
    cudaGetSymbolAddress((void**)&xt, g_xt);

    int gsmem = 2 * BSTG * 4;           // 40960
    cudaFuncSetAttribute(qkv_gemm, cudaFuncAttributeMaxDynamicSharedMemorySize, gsmem);
    cudaFuncSetAttribute(o_gemm,   cudaFuncAttributeMaxDynamicSharedMemorySize, gsmem);
    int asmem = 2 * ASTG * 4;           // 81920
    cudaFuncSetAttribute(flash_attn, cudaFuncAttributeMaxDynamicSharedMemorySize, asmem);

    // prepass: round + permute (+ transpose for weights)
    prep_act<<<ROWS * 1024 / 1024, 256>>>(x, xt);
    prep_w<<<dim3(10, 1024), 256>>>(Wq, Wk, Wv, Wo);

    qkv_gemm<<<dim3(24, ROWS / 128), 128, gsmem>>>(bq, bk, bv);
    flash_attn<<<dim3(SEQ / 128, NH, BATCH), 128, asmem>>>();
    o_gemm<<<dim3(16, ROWS / 128), 128, gsmem>>>(bo, out);
}

// round 10
// speedup vs baseline: 1.0774x; 1.0774x over previous
#include <cuda_runtime.h>
#include <cstdint>

#define D_MODEL 1024
#define NH 16
#define DK 64
#define BATCH 2
#define SEQ 2048
#define ROWS (BATCH*SEQ)

// Q prescale: (1/sqrt(64)) * log2(e)
#define QSCALE 0.18033688011112042f

// ---- scratch (no allocations allowed) ----
__device__ __align__(16) float g_xt [ROWS * 1024];
__device__ __align__(16) float g_wqt[1024 * 1024];
__device__ __align__(16) float g_wkt[256  * 1024];
__device__ __align__(16) float g_wvt[256  * 1024];
__device__ __align__(16) float g_wot[1024 * 1024];
__device__ __align__(16) float g_q  [ROWS * 1024];
__device__ __align__(16) float g_k  [ROWS * 256];
__device__ __align__(16) float g_vt [256  * ROWS];
__device__ __align__(16) float g_o  [ROWS * 1024];

__device__ __forceinline__ uint32_t f2tf(float x) {
    uint32_t y;
    asm("cvt.rna.tf32.f32 %0, %1;" : "=r"(y) : "f"(x));
    return y;
}
__device__ __forceinline__ float rndf(float x) { return __uint_as_float(f2tf(x)); }
__device__ __forceinline__ float ex2(float x) {
    float y;
    asm("ex2.approx.ftz.f32 %0, %1;" : "=f"(y) : "f"(x));
    return y;
}

// permuted position j (0..63) <-> feature k: j = tg*16 + kk*2 + s, k = kk*8 + tg + 4s
__device__ __forceinline__ int j16(int k)   { return (k & 3) * 16 + ((k >> 3) << 1) + ((k >> 2) & 1); }
__device__ __forceinline__ int sig64(int j) { return (((j >> 1) & 7) << 3) + (j >> 4) + ((j & 1) << 2); }

__device__ __forceinline__ void mma8(float* c, const uint32_t* a, const uint32_t* b) {
    asm volatile(
        "mma.sync.aligned.m16n8k8.row.col.f32.tf32.tf32.f32 "
        "{%0,%1,%2,%3},{%4,%5,%6,%7},{%8,%9},{%0,%1,%2,%3};"
        : "+f"(c[0]), "+f"(c[1]), "+f"(c[2]), "+f"(c[3])
        : "r"(a[0]), "r"(a[1]), "r"(a[2]), "r"(a[3]), "r"(b[0]), "r"(b[1]));
}

__device__ __forceinline__ void cpa16(uint32_t dst, const void* src) {
    asm volatile("cp.async.cg.shared.global [%0], [%1], 16;\n" :: "r"(dst), "l"(src) : "memory");
}
#define CP_COMMIT asm volatile("cp.async.commit_group;\n" ::: "memory")
#define CP_WAIT1  asm volatile("cp.async.wait_group 1;\n" ::: "memory")
#define CP_WAIT0  asm volatile("cp.async.wait_group 0;\n" ::: "memory")

#define GP 20
#define GPITCH 80
#define BPITCH 68   // compact B pitch: groups at tg*16 (16B-aligned, 2-way conflicts)

// ============================================================
// Prepass kernels
// ============================================================
__global__ __launch_bounds__(256) void prep_act(const float* __restrict__ in, float* __restrict__ out) {
    int i4 = (blockIdx.x * 256 + threadIdx.x) * 4;
    int base = i4 & ~63;
#pragma unroll
    for (int j = 0; j < 4; j++)
        out[i4 + j] = rndf(in[base + sig64((i4 + j) & 63)]);
}

__global__ __launch_bounds__(256) void prep_w(
    const float* __restrict__ Wq, const float* __restrict__ Wk,
    const float* __restrict__ Wv, const float* __restrict__ Wo)
{
    int col = blockIdx.x * 256 + threadIdx.x;
    int kp = blockIdx.y;
    int k = (kp & ~63) + sig64(kp & 63);
    const float* W; float* Wt; int N, n;
    if (col < 1024)      { W = Wq; Wt = g_wqt; N = 1024; n = col; }
    else if (col < 1280) { W = Wk; Wt = g_wkt; N = 256;  n = col - 1024; }
    else if (col < 1536) { W = Wv; Wt = g_wvt; N = 256;  n = col - 1280; }
    else                 { W = Wo; Wt = g_wot; N = 1024; n = col - 1536; }
    Wt[(size_t)n * 1024 + kp] = rndf(W[(size_t)k * N + n]);
}

// ============================================================
// GEMM v2: C[M,N] = A[M,1024] @ Bt[N,1024]^T + bias
// CTA tile 128(M) x 256(N), BK=64, 256 threads, 8 warps (2x4) of 64x64.
// A staged pitch-80 (conflict-free), B staged pitch-68 (compact, 2-way).
// cp.async double buffer; L2-roofline-clear tile (0.047 B/MAC).
// ============================================================
#define GA_WORDS (128 * GPITCH)            // 10240 words = 40960 B
#define GB_WORDS (256 * BPITCH)            // 17408 words = 69632 B
#define GSTG_WORDS (GA_WORDS + GB_WORDS)   // 27648 words = 110592 B
#define GSMEM_BYTES (2 * GSTG_WORDS * 4)   // 221184 B

__device__ __forceinline__ void cp_stage_g(uint32_t sb, int stage,
                                           const float* Ab, const float* Bb,
                                           int kt, int tid) {
    uint32_t base = sb + (uint32_t)stage * (GSTG_WORDS * 4);
    const float* As = Ab + kt * 64;
    const float* Bs = Bb + kt * 64;
#pragma unroll
    for (int t = 0; t < 8; t++) {          // A: 2048 chunks of 16B
        int i = tid + t * 256; int row = i >> 4, ch = i & 15;
        cpa16(base + (uint32_t)(row * GPITCH + (ch >> 2) * GP + (ch & 3) * 4) * 4,
              As + (size_t)row * 1024 + ch * 4);
    }
#pragma unroll
    for (int t = 0; t < 16; t++) {         // B: 4096 chunks of 16B
        int i = tid + t * 256; int row = i >> 4, ch = i & 15;
        cpa16(base + (uint32_t)(GA_WORDS + row * BPITCH + ch * 4) * 4,
              Bs + (size_t)row * 1024 + ch * 4);
    }
    CP_COMMIT;
}

template<int EPI>
__device__ __forceinline__ void gemm_body(
    const float* __restrict__ A, const float* __restrict__ Bt,
    const float* __restrict__ bias, float* __restrict__ C,
    int N, int bm, int bn)
{
    extern __shared__ uint32_t smg[];
    const int tid = threadIdx.x, lane = tid & 31, w = tid >> 5;
    const int g = lane >> 2, tg = lane & 3;
    const int wm = (w >> 2) * 64, wn = (w & 3) * 64;
    uint32_t sbase = (uint32_t)__cvta_generic_to_shared(smg);
    const float* Ab = A + (size_t)bm * 1024;
    const float* Bb = Bt + (size_t)bn * 1024;

    float acc[4][8][4];
#pragma unroll
    for (int i = 0; i < 4; i++)
#pragma unroll
        for (int j = 0; j < 8; j++)
#pragma unroll
            for (int q = 0; q < 4; q++) acc[i][j][q] = 0.f;

    cp_stage_g(sbase, 0, Ab, Bb, 0, tid);
    for (int kt = 0; kt < 16; kt++) {
        if (kt < 15) {
            cp_stage_g(sbase, (kt + 1) & 1, Ab, Bb, kt + 1, tid);
            CP_WAIT1;
        } else {
            CP_WAIT0;
        }
        __syncthreads();
        const uint32_t* Sa = smg + (kt & 1) * GSTG_WORDS;
        const uint32_t* Sb = Sa + GA_WORDS;

#pragma unroll
        for (int hh = 0; hh < 2; hh++) {
            // B fragments for this warp's 64 N-columns (8 nf rows x 2 uint4)
            uint4 b4[8][2];
#pragma unroll
            for (int nf = 0; nf < 8; nf++) {
                const uint4* p = (const uint4*)(Sb + (wn + nf * 8 + g) * BPITCH + tg * 16 + hh * 8);
                b4[nf][0] = p[0]; b4[nf][1] = p[1];
            }
#pragma unroll
            for (int mf = 0; mf < 4; mf++) {
                const uint4* pl = (const uint4*)(Sa + (wm + mf * 16 + g) * GPITCH + tg * GP + hh * 8);
                const uint4* ph = (const uint4*)(Sa + (wm + mf * 16 + g + 8) * GPITCH + tg * GP + hh * 8);
                uint4 lo[2] = {pl[0], pl[1]}, hi[2] = {ph[0], ph[1]};
#pragma unroll
                for (int kkl = 0; kkl < 4; kkl++) {
                    int q = kkl >> 1; bool od = kkl & 1;
                    uint32_t a[4];
                    a[0] = od ? lo[q].z : lo[q].x;
                    a[2] = od ? lo[q].w : lo[q].y;
                    a[1] = od ? hi[q].z : hi[q].x;
                    a[3] = od ? hi[q].w : hi[q].y;
#pragma unroll
                    for (int nf = 0; nf < 8; nf++) {
                        uint32_t b[2];
                        b[0] = od ? b4[nf][q].z : b4[nf][q].x;
                        b[1] = od ? b4[nf][q].w : b4[nf][q].y;
                        mma8(acc[mf][nf], a, b);
                    }
                }
            }
        }
        __syncthreads();
    }

#pragma unroll
    for (int mf = 0; mf < 4; mf++)
#pragma unroll
        for (int nf = 0; nf < 8; nf++) {
            int r0 = bm + wm + mf * 16 + g;
            int c0 = bn + wn + nf * 8 + tg * 2;
            float b0 = bias[c0], b1 = bias[c0 + 1];
            float v00 = acc[mf][nf][0] + b0, v01 = acc[mf][nf][1] + b1;
            float v10 = acc[mf][nf][2] + b0, v11 = acc[mf][nf][3] + b1;
            if (EPI == 0) {
                C[(size_t)r0 * N + c0]           = v00;
                C[(size_t)r0 * N + c0 + 1]       = v01;
                C[(size_t)(r0 + 8) * N + c0]     = v10;
                C[(size_t)(r0 + 8) * N + c0 + 1] = v11;
            } else if (EPI == 1 || EPI == 3) {
                if (EPI == 3) { v00 *= QSCALE; v01 *= QSCALE; v10 *= QSCALE; v11 *= QSCALE; }
                int cb = c0 & ~63;
                int ja = cb + j16(c0 & 63), jb = cb + j16((c0 + 1) & 63);
                C[(size_t)r0 * N + ja]       = rndf(v00);
                C[(size_t)r0 * N + jb]       = rndf(v01);
                C[(size_t)(r0 + 8) * N + ja] = rndf(v10);
                C[(size_t)(r0 + 8) * N + jb] = rndf(v11);
            } else {  // V transpose: g_vt[feature][token-permuted]
                int ra = (r0 & ~63) + j16(r0 & 63);
                int rb = (r0 & ~63) + j16((r0 + 8) & 63);
                C[(size_t)c0 * ROWS + ra]       = rndf(v00);
                C[(size_t)(c0 + 1) * ROWS + ra] = rndf(v01);
                C[(size_t)c0 * ROWS + rb]       = rndf(v10);
                C[(size_t)(c0 + 1) * ROWS + rb] = rndf(v11);
            }
        }
}

// qkv: grid (6, 32): bx 0..3 = Q n-blocks of 256, 4 = K, 5 = V
__global__ __launch_bounds__(256) void qkv_gemm(
    const float* __restrict__ bq, const float* __restrict__ bk, const float* __restrict__ bv)
{
    int bx = blockIdx.x, bm = blockIdx.y * 128;
    if (bx < 4)       gemm_body<3>(g_xt, g_wqt, bq, g_q,  1024, bm, bx * 256);
    else if (bx == 4) gemm_body<1>(g_xt, g_wkt, bk, g_k,  256,  bm, 0);
    else              gemm_body<2>(g_xt, g_wvt, bv, g_vt, 256,  bm, 0);
}

__global__ __launch_bounds__(256) void o_gemm(const float* __restrict__ bo, float* __restrict__ out)
{
    gemm_body<0>(g_o, g_wot, bo, out, 1024, blockIdx.y * 128, blockIdx.x * 256);
}

// ============================================================
// Flash attention (reproduced-best config): one-pass softmax,
// per-k-pair pipeline, 128 threads (4 warps x 32 q-rows), Q-tile 128,
// KV-tile 64, cp.async double buffer. grid (SEQ/128, NH, BATCH).
// ============================================================
#define ASTG (128 * GPITCH)

__device__ __forceinline__ void cp_stage_attn(uint32_t sb, const float* Kp, const float* Vp, int tid) {
#pragma unroll
    for (int t = 0; t < 8; t++) {
        int cid = tid + t * 128; int row = cid >> 4, ch = cid & 15;
        cpa16(sb + (uint32_t)(row * GPITCH + (ch >> 2) * GP + (ch & 3) * 4) * 4,
              Kp + (size_t)row * 256 + ch * 4);
    }
#pragma unroll
    for (int t = 0; t < 8; t++) {
        int cid = tid + t * 128; int row = cid >> 4, ch = cid & 15;
        cpa16(sb + (uint32_t)((64 + row) * GPITCH + (ch >> 2) * GP + (ch & 3) * 4) * 4,
              Vp + (size_t)row * ROWS + ch * 4);
    }
    CP_COMMIT;
}

__global__ __launch_bounds__(128, 2) void flash_attn()
{
    extern __shared__ uint32_t sm[];
    const int qt = blockIdx.x, h = blockIdx.y, b = blockIdx.z;
    const int kvh = h >> 2;
    const int tid = threadIdx.x, lane = tid & 31, w = tid >> 5;
    const int g = lane >> 2, tg = lane & 3;
    const int q0 = w * 32;
    uint32_t sbase = (uint32_t)__cvta_generic_to_shared(sm);
    const int srcA = (lane & ~3) + (tg >> 1), srcB = srcA + 2;
    const bool oddt = tg & 1;

    uint32_t aQ[2][8][4];
#pragma unroll
    for (int mf = 0; mf < 2; mf++)
#pragma unroll
        for (int rr = 0; rr < 2; rr++) {
            int row = b * SEQ + qt * 128 + q0 + mf * 16 + g + rr * 8;
            const uint4* qp = (const uint4*)(g_q + (size_t)row * 1024 + h * 64 + tg * 16);
            uint4 u[4] = {qp[0], qp[1], qp[2], qp[3]};
#pragma unroll
            for (int q = 0; q < 4; q++) {
                aQ[mf][2 * q][rr]         = __float_as_uint(((const float*)&u[q])[0]);
                aQ[mf][2 * q][2 + rr]     = __float_as_uint(((const float*)&u[q])[1]);
                aQ[mf][2 * q + 1][rr]     = __float_as_uint(((const float*)&u[q])[2]);
                aQ[mf][2 * q + 1][2 + rr] = __float_as_uint(((const float*)&u[q])[3]);
            }
        }

    float accO[2][8][4];
#pragma unroll
    for (int mf = 0; mf < 2; mf++)
#pragma unroll
        for (int i = 0; i < 8; i++)
#pragma unroll
            for (int j = 0; j < 4; j++) accO[mf][i][j] = 0.f;
    float lsum[2][2] = {{0.f, 0.f}, {0.f, 0.f}};

    const float* Kbase = g_k + (size_t)(b * SEQ) * 256 + kvh * 64;
    const float* Vbase = g_vt + (size_t)(kvh * 64) * ROWS + (size_t)b * SEQ;

    cp_stage_attn(sbase, Kbase, Vbase, tid);
    for (int kt = 0; kt < SEQ / 64; kt++) {
        if (kt < SEQ / 64 - 1) {
            cp_stage_attn(sbase + (uint32_t)(((kt + 1) & 1) * ASTG * 4),
                          Kbase + (size_t)(kt + 1) * 64 * 256, Vbase + (kt + 1) * 64, tid);
            CP_WAIT1;
        } else {
            CP_WAIT0;
        }
        __syncthreads();
        const uint32_t* Ks = sm + (kt & 1) * ASTG;
        const uint32_t* Vs = Ks + 64 * GPITCH;

        float s[2][2][2][4];

#pragma unroll
        for (int nl = 0; nl < 2; nl++) {
            const uint4* kp = (const uint4*)(Ks + (nl * 8 + g) * GPITCH + tg * GP);
            uint4 kf[4] = {kp[0], kp[1], kp[2], kp[3]};
#pragma unroll
            for (int q = 0; q < 4; q++) { s[0][0][nl][q] = 0.f; s[0][1][nl][q] = 0.f; }
#pragma unroll
            for (int kk = 0; kk < 8; kk++) {
                const uint4& f = kf[kk >> 1];
                uint32_t bb[2];
                bb[0] = (kk & 1) ? f.z : f.x;
                bb[1] = (kk & 1) ? f.w : f.y;
                mma8(s[0][0][nl], aQ[0][kk], bb);
                mma8(s[0][1][nl], aQ[1][kk], bb);
            }
        }

#pragma unroll
        for (int jp = 0; jp < 4; jp++) {
            const int cur = jp & 1, nxt = cur ^ 1;
            if (jp < 3) {
#pragma unroll
                for (int nl = 0; nl < 2; nl++) {
                    int nf = (jp + 1) * 2 + nl;
                    const uint4* kp = (const uint4*)(Ks + (nf * 8 + g) * GPITCH + tg * GP);
                    uint4 kf[4] = {kp[0], kp[1], kp[2], kp[3]};
#pragma unroll
                    for (int q = 0; q < 4; q++) { s[nxt][0][nl][q] = 0.f; s[nxt][1][nl][q] = 0.f; }
#pragma unroll
                    for (int kk = 0; kk < 8; kk++) {
                        const uint4& f = kf[kk >> 1];
                        uint32_t bb[2];
                        bb[0] = (kk & 1) ? f.z : f.x;
                        bb[1] = (kk & 1) ? f.w : f.y;
                        mma8(s[nxt][0][nl], aQ[0][kk], bb);
                        mma8(s[nxt][1][nl], aQ[1][kk], bb);
                    }
                }
            }

#pragma unroll
            for (int mf = 0; mf < 2; mf++)
#pragma unroll
                for (int nl = 0; nl < 2; nl++) {
                    float p0 = ex2(s[cur][mf][nl][0]);
                    float p1 = ex2(s[cur][mf][nl][1]);
                    float p2 = ex2(s[cur][mf][nl][2]);
                    float p3 = ex2(s[cur][mf][nl][3]);
                    lsum[mf][0] += p0 + p1;
                    lsum[mf][1] += p2 + p3;
                    uint32_t t0 = f2tf(p0), t1 = f2tf(p1), t2 = f2tf(p2), t3 = f2tf(p3);
                    uint32_t u0 = __shfl_sync(0xffffffffu, t0, srcA);
                    uint32_t u1 = __shfl_sync(0xffffffffu, t1, srcA);
                    uint32_t w0 = __shfl_sync(0xffffffffu, t0, srcB);
                    uint32_t w1 = __shfl_sync(0xffffffffu, t1, srcB);
                    uint32_t v0 = __shfl_sync(0xffffffffu, t2, srcA);
                    uint32_t v1 = __shfl_sync(0xffffffffu, t3, srcA);
                    uint32_t x0 = __shfl_sync(0xffffffffu, t2, srcB);
                    uint32_t x1 = __shfl_sync(0xffffffffu, t3, srcB);
                    s[cur][mf][nl][0] = __uint_as_float(oddt ? u1 : u0);
                    s[cur][mf][nl][2] = __uint_as_float(oddt ? w1 : w0);
                    s[cur][mf][nl][1] = __uint_as_float(oddt ? v1 : v0);
                    s[cur][mf][nl][3] = __uint_as_float(oddt ? x1 : x0);
                }

#pragma unroll
            for (int nf = 0; nf < 8; nf++) {
                const uint4* vp = (const uint4*)(Vs + (nf * 8 + g) * GPITCH + tg * GP);
                uint4 vf = vp[jp];
                uint32_t bb0[2] = {vf.x, vf.y};
                uint32_t bb1[2] = {vf.z, vf.w};
                mma8(accO[0][nf], (const uint32_t*)s[cur][0][0], bb0);
                mma8(accO[0][nf], (const uint32_t*)s[cur][0][1], bb1);
                mma8(accO[1][nf], (const uint32_t*)s[cur][1][0], bb0);
                mma8(accO[1][nf], (const uint32_t*)s[cur][1][1], bb1);
            }
        }
        __syncthreads();
    }

#pragma unroll
    for (int mf = 0; mf < 2; mf++) {
        float l0 = lsum[mf][0], l1 = lsum[mf][1];
        l0 += __shfl_xor_sync(0xffffffffu, l0, 1);
        l0 += __shfl_xor_sync(0xffffffffu, l0, 2);
        l1 += __shfl_xor_sync(0xffffffffu, l1, 1);
        l1 += __shfl_xor_sync(0xffffffffu, l1, 2);
        float inv0 = 1.f / l0, inv1 = 1.f / l1;
        int rbase = b * SEQ + qt * 128 + q0 + mf * 16 + g;
        float* Op = g_o + (size_t)rbase * 1024 + h * 64;
#pragma unroll
        for (int nf = 0; nf < 8; nf++) {
            int c = nf * 8 + tg * 2;
            int ja = j16(c), jb = j16(c + 1);
            Op[ja] = rndf(accO[mf][nf][0] * inv0);
            Op[jb] = rndf(accO[mf][nf][1] * inv0);
            Op[(size_t)8 * 1024 + ja] = rndf(accO[mf][nf][2] * inv1);
            Op[(size_t)8 * 1024 + jb] = rndf(accO[mf][nf][3] * inv1);
        }
    }
}

// ============================================================
extern "C" void kernel_launch(void* const* d_in, const int* in_sizes, int n_in,
                              void* d_out, int out_size)
{
    const float* x  = (const float*)d_in[0];
    const float* Wq = (const float*)d_in[1];
    const float* bq = (const float*)d_in[2];
    const float* Wk = (const float*)d_in[3];
    const float* bk = (const float*)d_in[4];
    const float* Wv = (const float*)d_in[5];
    const float* bv = (const float*)d_in[6];
    const float* Wo = (const float*)d_in[7];
    const float* bo = (const float*)d_in[8];
    float* out = (float*)d_out;

    float* xt;
    cudaGetSymbolAddress((void**)&xt, g_xt);

    cudaFuncSetAttribute(qkv_gemm, cudaFuncAttributeMaxDynamicSharedMemorySize, GSMEM_BYTES);
    cudaFuncSetAttribute(o_gemm,   cudaFuncAttributeMaxDynamicSharedMemorySize, GSMEM_BYTES);
    int asmem = 2 * ASTG * 4;           // 81920
    cudaFuncSetAttribute(flash_attn, cudaFuncAttributeMaxDynamicSharedMemorySize, asmem);

    prep_act<<<ROWS * 1024 / 1024, 256>>>(x, xt);
    prep_w<<<dim3(10, 1024), 256>>>(Wq, Wk, Wv, Wo);

    qkv_gemm<<<dim3(6, ROWS / 128), 256, GSMEM_BYTES>>>(bq, bk, bv);
    flash_attn<<<dim3(SEQ / 128, NH, BATCH), 128, asmem>>>();
    o_gemm<<<dim3(4, ROWS / 128), 256, GSMEM_BYTES>>>(bo, out);
}